// round 2
// baseline (speedup 1.0000x reference)
#include <cuda_runtime.h>

// EnergyModel: energy[t] = sum_q qa[q] * sum_f w[f]*(desc[t,q,f]-qf[t,q,f])^2
// with range masking on T[:,4:7]. HBM-bound streaming reduction.
//
// R2: split each row into SPLIT query-chunks for fine-grained SM load balance
// (only ~1/3 of rows are active; coarse 1-CTA-per-row left 37% of HBM idle).
// Deterministic two-kernel scheme: partials -> fold (no atomics).

#define NQ 128
#define FDIM 576                    // 64*1 + 64*3 + 64*5
#define NGRP 192
#define SPLIT 8
#define QPC (NQ / SPLIT)            // 16 queries per chunk
#define THREADS 256
#define F4_PER_ROW (FDIM / 4)       // 144
#define F4_TOTAL (NQ * F4_PER_ROW)  // 18432 float4 per t per tensor
#define CHUNK_F4 (QPC * F4_PER_ROW) // 2304 float4 per chunk per tensor

__device__ float g_partial[1024 * SPLIT];

__global__ void __launch_bounds__(THREADS)
partial_kernel(const float* __restrict__ T,
               const float4* __restrict__ desc,
               const float4* __restrict__ qf,
               const float* __restrict__ qa,
               const float* __restrict__ logit,
               const float* __restrict__ ranges)
{
    const int bx  = blockIdx.x;
    const int t   = bx >> 3;         // SPLIT == 8
    const int c   = bx & (SPLIT - 1);
    const int tid = threadIdx.x;

    // Range mask: every thread computes the same predicate (uniform branch).
    // Masked rows never touch the 74KB payload; finalize writes 1e5.
    {
        const float x0 = T[t * 7 + 4];
        const float x1 = T[t * 7 + 5];
        const float x2 = T[t * 7 + 6];
        const bool ok = (ranges[1] >= x0) && (x0 >= ranges[0]) &&
                        (ranges[3] >= x1) && (x1 >= ranges[2]) &&
                        (ranges[5] >= x2) && (x2 >= ranges[4]);
        if (!ok) return;
    }

    __shared__ float s_w[FDIM];
    __shared__ float s_qa[QPC];
    __shared__ float s_red[THREADS / 32];

    // Expand per-irrep-copy softplus weight to per-feature weight.
    const float inv = 1.0f / (0.6931471805599453f * (float)NGRP);
    for (int f = tid; f < FDIM; f += THREADS) {
        int g;
        if (f < 64)        g = f;                    // l=0, d=1
        else if (f < 256)  g = 64 + (f - 64) / 3;    // l=1, d=3
        else               g = 128 + (f - 256) / 5;  // l=2, d=5
        const float x  = logit[g];
        const float sp = fmaxf(x, 0.0f) + log1pf(expf(-fabsf(x)));
        s_w[f] = 2.0f * sp * inv;
    }
    if (tid < QPC) s_qa[tid] = qa[c * QPC + tid];
    __syncthreads();

    const float4* db = desc + (size_t)t * F4_TOTAL + (size_t)c * CHUNK_F4;
    const float4* qb = qf   + (size_t)t * F4_TOTAL + (size_t)c * CHUNK_F4;

    float acc = 0.0f;
    #pragma unroll 3
    for (int j = tid; j < CHUNK_F4; j += THREADS) {   // 9 iterations
        const int q = j / F4_PER_ROW;
        const int f = (j - q * F4_PER_ROW) * 4;
        const float4 d = db[j];
        const float4 e = qb[j];
        const float dx = d.x - e.x;
        const float dy = d.y - e.y;
        const float dz = d.z - e.z;
        const float dw = d.w - e.w;
        float s = s_w[f] * dx * dx;
        s = fmaf(s_w[f + 1], dy * dy, s);
        s = fmaf(s_w[f + 2], dz * dz, s);
        s = fmaf(s_w[f + 3], dw * dw, s);
        acc = fmaf(s_qa[q], s, acc);
    }

    #pragma unroll
    for (int o = 16; o > 0; o >>= 1)
        acc += __shfl_down_sync(0xffffffffu, acc, o);
    if ((tid & 31) == 0) s_red[tid >> 5] = acc;
    __syncthreads();
    if (tid < 32) {
        float v = (tid < THREADS / 32) ? s_red[tid] : 0.0f;
        #pragma unroll
        for (int o = 4; o > 0; o >>= 1)
            v += __shfl_down_sync(0xffffffffu, v, o);
        if (tid == 0) g_partial[bx] = v;
    }
}

__global__ void finalize_kernel(const float* __restrict__ T,
                                const float* __restrict__ ranges,
                                float* __restrict__ out,
                                int nt)
{
    const int t = blockIdx.x * blockDim.x + threadIdx.x;
    if (t >= nt) return;

    const float x0 = T[t * 7 + 4];
    const float x1 = T[t * 7 + 5];
    const float x2 = T[t * 7 + 6];
    const bool ok = (ranges[1] >= x0) && (x0 >= ranges[0]) &&
                    (ranges[3] >= x1) && (x1 >= ranges[2]) &&
                    (ranges[5] >= x2) && (x2 >= ranges[4]);
    if (!ok) {
        out[t] = 100000.0f;
        return;
    }
    float s = 0.0f;
    #pragma unroll
    for (int i = 0; i < SPLIT; i++)
        s += g_partial[t * SPLIT + i];
    out[t] = s;
}

extern "C" void kernel_launch(void* const* d_in, const int* in_sizes, int n_in,
                              void* d_out, int out_size)
{
    const float*  T      = (const float*)d_in[0];
    const float4* desc   = (const float4*)d_in[1];
    const float4* qf     = (const float4*)d_in[2];
    const float*  qa     = (const float*)d_in[3];
    const float*  logit  = (const float*)d_in[4];
    const float*  ranges = (const float*)d_in[5];
    float* out = (float*)d_out;

    const int nt = in_sizes[0] / 7;   // 1024

    partial_kernel<<<nt * SPLIT, THREADS>>>(T, desc, qf, qa, logit, ranges);
    finalize_kernel<<<(nt + 255) / 256, 256>>>(T, ranges, out, nt);
}